// round 1
// baseline (speedup 1.0000x reference)
#include <cuda_runtime.h>
#include <math.h>

// Problem constants
#define Bb   2
#define Ss   2048
#define Dd   1024
#define Hh   16
#define DKk  64
#define AUGC 192              // [K | Kr | Ki] augmented inner dim
#define BHh  (Bb * Hh)        // 32
#define Mm   (Bb * Ss)        // 4096

// Scratch (sanctioned: __device__ globals)
__device__ float  g_Qaug[(size_t)BHh * Ss * AUGC];  // [bh][s][192]
__device__ float  g_Kaug[(size_t)BHh * Ss * AUGC];
__device__ float  g_Vt  [(size_t)BHh * DKk * Ss];   // V transposed: [bh][dk][s]
__device__ float  g_O   [(size_t)Mm * Dd];          // head outputs, [b*s][h*64+dk]
__device__ float2 g_twid[1024];                     // FFT twiddles

// ---------------------------------------------------------------------------
// Twiddle init (fp64-accurate; twiddle error must be < ~4e-7 rel)
// ---------------------------------------------------------------------------
__global__ void twiddle_init_k() {
    int t = blockIdx.x * blockDim.x + threadIdx.x;
    if (t < 1024) {
        double ang = -2.0 * 3.14159265358979323846 * (double)t / 2048.0;
        double s, c;
        sincos(ang, &s, &c);
        g_twid[t] = make_float2((float)c, (float)s);
    }
}

// ---------------------------------------------------------------------------
// Generic fp32 SGEMM:  C = A * W^T (+bias), batched over blockIdx.z
//   A: [M, lda] row-major (k contiguous), W: [N, ldw] row-major (k contiguous)
//   NG: 1 -> BN=64, 2 -> BN=128.  BM=128, BK=8, 256 threads, 8x(4*NG) microtile
//   MODE 0: plain C[cbase + m*ldc + n]
//   MODE 1: scatter to aug layout   ((b*16+h)*2048+s)*192 + d
//   MODE 2: scatter to V^T layout   ((b*16+h)*64+d)*2048 + s
// ---------------------------------------------------------------------------
template<int NG, int MODE>
__global__ __launch_bounds__(256)
void sgemm_k(const float* __restrict__ A, size_t saZ,
             const float* __restrict__ W, size_t swZ,
             const float* __restrict__ bias,
             float* __restrict__ C, size_t scB1, size_t scB2, int Hdiv,
             int K, int lda, int ldw, int ldc)
{
    const int BM = 128, BK = 8;
    const int BN = 64 * NG;

    __shared__ float As[2][BK][BM];
    __shared__ float Ws[2][BK][BN];

    int z = blockIdx.z;
    const float* Ab = A + (size_t)z * saZ;
    const float* Wb = W + (size_t)z * swZ;
    size_t cbase = (size_t)(z / Hdiv) * scB1 + (size_t)(z % Hdiv) * scB2;

    int m0 = blockIdx.y * BM;
    int n0 = blockIdx.x * BN;
    int tid = threadIdx.x;
    int tx = tid & 15, ty = tid >> 4;
    int lr = tid >> 1;          // loader row 0..127
    int lc = (tid & 1) * 4;     // loader k-col 0 or 4

    float acc[8][4 * NG];
#pragma unroll
    for (int i = 0; i < 8; i++)
#pragma unroll
        for (int j = 0; j < 4 * NG; j++) acc[i][j] = 0.f;

    auto ldst = [&](int buf, int kt) {
        float4 av = *(const float4*)(Ab + (size_t)(m0 + lr) * lda + kt + lc);
        As[buf][lc + 0][lr] = av.x;
        As[buf][lc + 1][lr] = av.y;
        As[buf][lc + 2][lr] = av.z;
        As[buf][lc + 3][lr] = av.w;
        if (NG == 2 || tid < 128) {
            float4 wv = *(const float4*)(Wb + (size_t)(n0 + lr) * ldw + kt + lc);
            Ws[buf][lc + 0][lr] = wv.x;
            Ws[buf][lc + 1][lr] = wv.y;
            Ws[buf][lc + 2][lr] = wv.z;
            Ws[buf][lc + 3][lr] = wv.w;
        }
    };

    ldst(0, 0);
    __syncthreads();

    int nk = K / BK;
    for (int t = 0; t < nk; t++) {
        int buf = t & 1;
        if (t + 1 < nk) ldst(buf ^ 1, (t + 1) * BK);
#pragma unroll
        for (int kk = 0; kk < BK; kk++) {
            float a[8], b[4 * NG];
            *(float4*)&a[0] = *(const float4*)&As[buf][kk][ty * 4];
            *(float4*)&a[4] = *(const float4*)&As[buf][kk][ty * 4 + 64];
            *(float4*)&b[0] = *(const float4*)&Ws[buf][kk][tx * 4];
            if (NG == 2)
                *(float4*)&b[4] = *(const float4*)&Ws[buf][kk][tx * 4 + 64];
#pragma unroll
            for (int i = 0; i < 8; i++)
#pragma unroll
                for (int j = 0; j < 4 * NG; j++)
                    acc[i][j] = fmaf(a[i], b[j], acc[i][j]);
        }
        __syncthreads();
    }

    // writeout
#pragma unroll
    for (int gi = 0; gi < 2; gi++) {
#pragma unroll
        for (int i = 0; i < 4; i++) {
            int m = m0 + ty * 4 + gi * 64 + i;
#pragma unroll
            for (int gj = 0; gj < NG; gj++) {
                int n = n0 + tx * 4 + gj * 64;
                float4 v;
                v.x = acc[gi * 4 + i][gj * 4 + 0];
                v.y = acc[gi * 4 + i][gj * 4 + 1];
                v.z = acc[gi * 4 + i][gj * 4 + 2];
                v.w = acc[gi * 4 + i][gj * 4 + 3];
                if (bias) {
                    v.x += bias[n + 0];
                    v.y += bias[n + 1];
                    v.z += bias[n + 2];
                    v.w += bias[n + 3];
                }
                if (MODE == 0) {
                    *(float4*)(C + cbase + (size_t)m * ldc + n) = v;
                } else if (MODE == 1) {
                    int bb = m >> 11, s = m & 2047;
                    int hh = n >> 6,  d = n & 63;
                    *(float4*)(C + ((size_t)((bb * 16 + hh) * 2048 + s)) * AUGC + d) = v;
                } else {
                    int bb = m >> 11, s = m & 2047;
                    int hh = n >> 6,  d = n & 63;
                    float* cp = C + ((size_t)(bb * 16 + hh) * 64 + d) * 2048 + s;
                    cp[0 * 2048] = v.x;
                    cp[1 * 2048] = v.y;
                    cp[2 * 2048] = v.z;
                    cp[3 * 2048] = v.w;
                }
            }
        }
    }
}

// ---------------------------------------------------------------------------
// In-smem radix-2 FFT, length 2048, 2 lanes per CTA.
// grid = (32 bh, 2 tensor {Q,K}, 32 dk-pairs), 256 threads.
// Reads time lanes [0:64) of aug buffer, writes Re -> [64:128), Im -> [128:192).
// Q side gets tw/SCALE and fw/SCALE folded in; K side stays raw.
// ---------------------------------------------------------------------------
__global__ __launch_bounds__(256)
void fft_k(float* qaug, float* kaug, const float* twp, const float* fwp)
{
    __shared__ float  sr[2][2048];
    __shared__ float  si[2][2048];
    __shared__ float2 tw[1024];

    int bh     = blockIdx.x;
    int tensor = blockIdx.y;
    int dk0    = blockIdx.z * 2;
    float* base = (tensor == 0 ? qaug : kaug) + (size_t)bh * Ss * AUGC;
    int tid = threadIdx.x;

    for (int t = tid; t < 1024; t += 256) tw[t] = g_twid[t];

    for (int idx = tid; idx < 2 * Ss; idx += 256) {
        int l = idx & 1;
        int s = idx >> 1;
        float v = base[(size_t)s * AUGC + dk0 + l];
        int rs = __brev((unsigned)s) >> 21;   // 11-bit reversal
        sr[l][rs] = v;
        si[l][rs] = 0.f;
    }
    __syncthreads();

    for (int len = 2; len <= 2048; len <<= 1) {
        int half = len >> 1;
        int step = 2048 / len;
        for (int idx = tid; idx < 2048; idx += 256) {
            int l   = idx >> 10;
            int bix = idx & 1023;
            int grp = bix / half;
            int pos = bix - grp * half;
            int i0 = grp * len + pos;
            int i1 = i0 + half;
            float2 w = tw[pos * step];
            float xr = sr[l][i1], xi = si[l][i1];
            float tr = xr * w.x - xi * w.y;
            float ti = xr * w.y + xi * w.x;
            float ur = sr[l][i0], ui = si[l][i0];
            sr[l][i0] = ur + tr;  si[l][i0] = ui + ti;
            sr[l][i1] = ur - tr;  si[l][i1] = ui - ti;
        }
        __syncthreads();
    }

    float ft, ff;
    if (tensor == 0) { ft = twp[0] * 0.125f; ff = fwp[0] * 0.125f; }  // 1/SCALE = 1/8
    else             { ft = 1.f;             ff = 1.f; }

    for (int idx = tid; idx < 2 * Ss; idx += 256) {
        int l = idx & 1;
        int s = idx >> 1;
        size_t o = (size_t)s * AUGC + dk0 + l;
        if (tensor == 0) base[o] *= ft;
        base[o + 64]  = sr[l][s] * ff;
        base[o + 128] = si[l][s] * ff;
    }
}

// ---------------------------------------------------------------------------
// Row softmax, in place. One warp per 2048-wide row, row held in registers.
// ---------------------------------------------------------------------------
__global__ __launch_bounds__(256)
void softmax_k(float* __restrict__ attn)
{
    int warp = threadIdx.x >> 5;
    int lane = threadIdx.x & 31;
    size_t row = (size_t)blockIdx.x * 8 + warp;
    float4* p = (float4*)(attn + row * (size_t)Ss);

    float v[64];
    float mx = -3.4e38f;
#pragma unroll
    for (int i = 0; i < 16; i++) {
        float4 f = p[i * 32 + lane];
        v[4 * i + 0] = f.x; v[4 * i + 1] = f.y;
        v[4 * i + 2] = f.z; v[4 * i + 3] = f.w;
        mx = fmaxf(mx, fmaxf(fmaxf(f.x, f.y), fmaxf(f.z, f.w)));
    }
#pragma unroll
    for (int o = 16; o; o >>= 1) mx = fmaxf(mx, __shfl_xor_sync(0xffffffffu, mx, o));

    float sum = 0.f;
#pragma unroll
    for (int i = 0; i < 64; i++) { v[i] = expf(v[i] - mx); sum += v[i]; }
#pragma unroll
    for (int o = 16; o; o >>= 1) sum += __shfl_xor_sync(0xffffffffu, sum, o);
    float inv = 1.f / sum;

#pragma unroll
    for (int i = 0; i < 16; i++) {
        float4 f;
        f.x = v[4 * i + 0] * inv; f.y = v[4 * i + 1] * inv;
        f.z = v[4 * i + 2] * inv; f.w = v[4 * i + 3] * inv;
        p[i * 32 + lane] = f;
    }
}

// ---------------------------------------------------------------------------
extern "C" void kernel_launch(void* const* d_in, const int* in_sizes, int n_in,
                              void* d_out, int out_size)
{
    const float* x  = (const float*)d_in[0];
    const float* Wq = (const float*)d_in[1];
    const float* bq = (const float*)d_in[2];
    const float* Wk = (const float*)d_in[3];
    const float* bk = (const float*)d_in[4];
    const float* Wv = (const float*)d_in[5];
    const float* bv = (const float*)d_in[6];
    const float* Wo = (const float*)d_in[7];
    const float* bo = (const float*)d_in[8];
    const float* tw = (const float*)d_in[9];
    const float* fw = (const float*)d_in[10];

    float* out  = (float*)d_out;                         // [B,S,D]
    float* attn = out + (size_t)Mm * Dd;                 // [B,H,S,S]

    float *qaug, *kaug, *vt, *oo;
    cudaGetSymbolAddress((void**)&qaug, g_Qaug);
    cudaGetSymbolAddress((void**)&kaug, g_Kaug);
    cudaGetSymbolAddress((void**)&vt,   g_Vt);
    cudaGetSymbolAddress((void**)&oo,   g_O);

    dim3 blk(256);

    // 1-3: projections. M=4096, N=1024, K=1024.
    sgemm_k<2, 1><<<dim3(8, 32, 1), blk>>>(x, 0, Wq, 0, bq, qaug, 0, 0, 1,
                                           Dd, Dd, Dd, 0);
    sgemm_k<2, 1><<<dim3(8, 32, 1), blk>>>(x, 0, Wk, 0, bk, kaug, 0, 0, 1,
                                           Dd, Dd, Dd, 0);
    sgemm_k<2, 2><<<dim3(8, 32, 1), blk>>>(x, 0, Wv, 0, bv, vt, 0, 0, 1,
                                           Dd, Dd, Dd, 0);

    // 4-5: FFT of Q,K time lanes -> Re/Im lanes (+ scale folding on Q side)
    twiddle_init_k<<<4, 256>>>();
    fft_k<<<dim3(BHh, 2, 32), blk>>>(qaug, kaug, tw, fw);

    // 6: scores = Qaug * Kaug^T, batched over 32 heads, K=192 -> attn region (raw logits)
    sgemm_k<2, 0><<<dim3(16, 16, BHh), blk>>>(
        qaug, (size_t)Ss * AUGC, kaug, (size_t)Ss * AUGC, nullptr,
        attn, (size_t)Ss * Ss, 0, 1,
        AUGC, AUGC, AUGC, Ss);

    // 7: softmax in place (65536 rows, 8 rows per CTA)
    softmax_k<<<(BHh * Ss) / 8, blk>>>(attn);

    // 8: O = attn * V  (V stored transposed: [bh][dk][s]); out to [b*s][h*64+dk]
    sgemm_k<1, 0><<<dim3(1, 16, BHh), blk>>>(
        attn, (size_t)Ss * Ss, vt, (size_t)DKk * Ss, nullptr,
        oo, (size_t)Ss * Dd, 64, Hh,
        Ss, Ss, Ss, Dd);

    // 9: out = O * Wo^T + bo
    sgemm_k<2, 0><<<dim3(8, 32, 1), blk>>>(
        oo, 0, Wo, 0, bo,
        out, 0, 0, 1,
        Dd, Dd, Dd, Dd);
}

// round 4
// speedup vs baseline: 1.0636x; 1.0636x over previous
#include <cuda_runtime.h>
#include <math.h>
#include <stdint.h>

// Problem constants
#define Bb   2
#define Ss   2048
#define Dd   1024
#define Hh   16
#define DKk  64
#define AUGC 192              // [time | Re | Im]
#define EXTC 576              // [hi | hi | lo] / [hi | lo | hi]
#define BHh  (Bb * Hh)        // 32
#define Mm   (Bb * Ss)        // 4096
#define NPART 32              // softmax partials per row: 8 ntiles x 4 wn-warps

// Scratch
__device__ float  g_Qaug[(size_t)BHh * Ss * AUGC];
__device__ float  g_Kaug[(size_t)BHh * Ss * AUGC];
__device__ float  g_Qext[(size_t)BHh * Ss * EXTC];
__device__ float  g_Kext[(size_t)BHh * Ss * EXTC];
__device__ float  g_Vt  [(size_t)BHh * DKk * Ss];
__device__ float  g_O   [(size_t)Mm * Dd];
__device__ float  g_pmax[(size_t)BHh * Ss * NPART];
__device__ float  g_psum[(size_t)BHh * Ss * NPART];
__device__ float  g_rowm[(size_t)BHh * Ss];
__device__ float  g_rowz[(size_t)BHh * Ss];
__device__ float2 g_twid[1024];

// ---------------------------------------------------------------------------
// Twiddle init (fp64-accurate)
// ---------------------------------------------------------------------------
__global__ void twiddle_init_k() {
    int t = blockIdx.x * blockDim.x + threadIdx.x;
    if (t < 1024) {
        double ang = -2.0 * 3.14159265358979323846 * (double)t / 2048.0;
        double s, c;
        sincos(ang, &s, &c);
        g_twid[t] = make_float2((float)c, (float)s);
    }
}

// ---------------------------------------------------------------------------
// Generic fp32 SGEMM (known-good): C = A * W^T (+bias)
// ---------------------------------------------------------------------------
template<int NG, int MODE>
__global__ __launch_bounds__(256)
void sgemm_k(const float* __restrict__ A, size_t saZ,
             const float* __restrict__ W, size_t swZ,
             const float* __restrict__ bias,
             float* __restrict__ C, size_t scB1, size_t scB2, int Hdiv,
             int K, int lda, int ldw, int ldc)
{
    const int BM = 128, BK = 8;
    const int BN = 64 * NG;
    __shared__ float As[2][BK][BM];
    __shared__ float Ws[2][BK][BN];

    int z = blockIdx.z;
    const float* Ab = A + (size_t)z * saZ;
    const float* Wb = W + (size_t)z * swZ;
    size_t cbase = (size_t)(z / Hdiv) * scB1 + (size_t)(z % Hdiv) * scB2;

    int m0 = blockIdx.y * BM;
    int n0 = blockIdx.x * BN;
    int tid = threadIdx.x;
    int tx = tid & 15, ty = tid >> 4;
    int lr = tid >> 1;
    int lc = (tid & 1) * 4;

    float acc[8][4 * NG];
#pragma unroll
    for (int i = 0; i < 8; i++)
#pragma unroll
        for (int j = 0; j < 4 * NG; j++) acc[i][j] = 0.f;

    auto ldst = [&](int buf, int kt) {
        float4 av = *(const float4*)(Ab + (size_t)(m0 + lr) * lda + kt + lc);
        As[buf][lc + 0][lr] = av.x;
        As[buf][lc + 1][lr] = av.y;
        As[buf][lc + 2][lr] = av.z;
        As[buf][lc + 3][lr] = av.w;
        if (NG == 2 || tid < 128) {
            float4 wv = *(const float4*)(Wb + (size_t)(n0 + lr) * ldw + kt + lc);
            Ws[buf][lc + 0][lr] = wv.x;
            Ws[buf][lc + 1][lr] = wv.y;
            Ws[buf][lc + 2][lr] = wv.z;
            Ws[buf][lc + 3][lr] = wv.w;
        }
    };

    ldst(0, 0);
    __syncthreads();

    int nk = K / BK;
    for (int t = 0; t < nk; t++) {
        int buf = t & 1;
        if (t + 1 < nk) ldst(buf ^ 1, (t + 1) * BK);
#pragma unroll
        for (int kk = 0; kk < BK; kk++) {
            float a[8], b[4 * NG];
            *(float4*)&a[0] = *(const float4*)&As[buf][kk][ty * 4];
            *(float4*)&a[4] = *(const float4*)&As[buf][kk][ty * 4 + 64];
            *(float4*)&b[0] = *(const float4*)&Ws[buf][kk][tx * 4];
            if (NG == 2)
                *(float4*)&b[4] = *(const float4*)&Ws[buf][kk][tx * 4 + 64];
#pragma unroll
            for (int i = 0; i < 8; i++)
#pragma unroll
                for (int j = 0; j < 4 * NG; j++)
                    acc[i][j] = fmaf(a[i], b[j], acc[i][j]);
        }
        __syncthreads();
    }

#pragma unroll
    for (int gi = 0; gi < 2; gi++) {
#pragma unroll
        for (int i = 0; i < 4; i++) {
            int m = m0 + ty * 4 + gi * 64 + i;
#pragma unroll
            for (int gj = 0; gj < NG; gj++) {
                int n = n0 + tx * 4 + gj * 64;
                float4 v;
                v.x = acc[gi * 4 + i][gj * 4 + 0];
                v.y = acc[gi * 4 + i][gj * 4 + 1];
                v.z = acc[gi * 4 + i][gj * 4 + 2];
                v.w = acc[gi * 4 + i][gj * 4 + 3];
                if (bias) {
                    v.x += bias[n + 0]; v.y += bias[n + 1];
                    v.z += bias[n + 2]; v.w += bias[n + 3];
                }
                if (MODE == 0) {
                    *(float4*)(C + cbase + (size_t)m * ldc + n) = v;
                } else if (MODE == 1) {
                    int bb = m >> 11, s = m & 2047;
                    int hh = n >> 6,  d = n & 63;
                    *(float4*)(C + ((size_t)((bb * 16 + hh) * 2048 + s)) * AUGC + d) = v;
                } else {
                    int bb = m >> 11, s = m & 2047;
                    int hh = n >> 6,  d = n & 63;
                    float* cp = C + ((size_t)(bb * 16 + hh) * 64 + d) * 2048 + s;
                    cp[0 * 2048] = v.x; cp[1 * 2048] = v.y;
                    cp[2 * 2048] = v.z; cp[3 * 2048] = v.w;
                }
            }
        }
    }
}

// ---------------------------------------------------------------------------
// FFT (known-good)
// ---------------------------------------------------------------------------
__global__ __launch_bounds__(256)
void fft_k(float* qaug, float* kaug, const float* twp, const float* fwp)
{
    __shared__ float  sr[2][2048];
    __shared__ float  si[2][2048];
    __shared__ float2 tw[1024];

    int bh     = blockIdx.x;
    int tensor = blockIdx.y;
    int dk0    = blockIdx.z * 2;
    float* base = (tensor == 0 ? qaug : kaug) + (size_t)bh * Ss * AUGC;
    int tid = threadIdx.x;

    for (int t = tid; t < 1024; t += 256) tw[t] = g_twid[t];

    for (int idx = tid; idx < 2 * Ss; idx += 256) {
        int l = idx & 1;
        int s = idx >> 1;
        float v = base[(size_t)s * AUGC + dk0 + l];
        int rs = __brev((unsigned)s) >> 21;
        sr[l][rs] = v;
        si[l][rs] = 0.f;
    }
    __syncthreads();

    for (int len = 2; len <= 2048; len <<= 1) {
        int half = len >> 1;
        int step = 2048 / len;
        for (int idx = tid; idx < 2048; idx += 256) {
            int l   = idx >> 10;
            int bix = idx & 1023;
            int grp = bix / half;
            int pos = bix - grp * half;
            int i0 = grp * len + pos;
            int i1 = i0 + half;
            float2 w = tw[pos * step];
            float xr = sr[l][i1], xi = si[l][i1];
            float tr = xr * w.x - xi * w.y;
            float ti = xr * w.y + xi * w.x;
            float ur = sr[l][i0], ui = si[l][i0];
            sr[l][i0] = ur + tr;  si[l][i0] = ui + ti;
            sr[l][i1] = ur - tr;  si[l][i1] = ui - ti;
        }
        __syncthreads();
    }

    float ft, ff;
    if (tensor == 0) { ft = twp[0] * 0.125f; ff = fwp[0] * 0.125f; }
    else             { ft = 1.f;             ff = 1.f; }

    for (int idx = tid; idx < 2 * Ss; idx += 256) {
        int l = idx & 1;
        int s = idx >> 1;
        size_t o = (size_t)s * AUGC + dk0 + l;
        if (tensor == 0) base[o] *= ft;
        base[o + 64]  = sr[l][s] * ff;
        base[o + 128] = si[l][s] * ff;
    }
}

// ---------------------------------------------------------------------------
// Convert aug (192) -> tf32 hi/lo ext (576). Both hi AND lo tf32-rounded.
// QMODE=1: [hi|hi|lo] ; QMODE=0: [hi|lo|hi]
// ---------------------------------------------------------------------------
__device__ __forceinline__ float tf32r(float x) {
    uint32_t u;
    asm("cvt.rna.tf32.f32 %0, %1;" : "=r"(u) : "f"(x));
    return __uint_as_float(u);
}
template<int QMODE>
__global__ __launch_bounds__(256)
void convert_k(const float* __restrict__ src, float* __restrict__ dst)
{
    size_t i4 = (size_t)blockIdx.x * 256 + threadIdx.x;
    size_t row = i4 / 48;
    int c4 = (int)(i4 % 48);
    float4 x = ((const float4*)src)[i4];
    float4 h, l;
    h.x = tf32r(x.x); l.x = tf32r(x.x - h.x);
    h.y = tf32r(x.y); l.y = tf32r(x.y - h.y);
    h.z = tf32r(x.z); l.z = tf32r(x.z - h.z);
    h.w = tf32r(x.w); l.w = tf32r(x.w - h.w);
    float4* drow = (float4*)(dst + row * EXTC);
    drow[c4] = h;
    if (QMODE) { drow[48 + c4] = h; drow[96 + c4] = l; }
    else       { drow[48 + c4] = l; drow[96 + c4] = h; }
}

// ---------------------------------------------------------------------------
// Scores via mma.sync tf32 (K=576). CTA tile 128x256, 8 warps @64x64, BK=32.
// Epilogue: raw logits -> attn, per-(row, ntile, wn) softmax partials.
// grid = (8 ntiles, 16 mtiles, 32 bh), 256 threads, dyn smem 110592B
// ---------------------------------------------------------------------------
#define ASTR 36
#define ABUF (128 * ASTR)
#define BBUF (256 * ASTR)

__device__ __forceinline__ void mma_tf32(float c[4], const uint32_t a[4],
                                         const uint32_t b[2]) {
    asm volatile(
        "mma.sync.aligned.m16n8k8.row.col.f32.tf32.tf32.f32 "
        "{%0,%1,%2,%3}, {%4,%5,%6,%7}, {%8,%9}, {%0,%1,%2,%3};"
        : "+f"(c[0]), "+f"(c[1]), "+f"(c[2]), "+f"(c[3])
        : "r"(a[0]), "r"(a[1]), "r"(a[2]), "r"(a[3]), "r"(b[0]), "r"(b[1]));
}

__global__ __launch_bounds__(256, 1)
void scores_mma_k(const float* __restrict__ Qe, const float* __restrict__ Ke,
                  float* __restrict__ attn,
                  float* __restrict__ pmax, float* __restrict__ psum)
{
    extern __shared__ float sm[];
    float* AsB = sm;                  // [2][128][36]
    float* BsB = sm + 2 * ABUF;       // [2][256][36]

    const int tid  = threadIdx.x;
    const int wid  = tid >> 5;
    const int lane = tid & 31;
    const int g    = lane >> 2;
    const int tig  = lane & 3;
    const int wm   = wid >> 2;        // 0..1
    const int wn   = wid & 3;         // 0..3

    const int ntile = blockIdx.x;
    const int mtile = blockIdx.y;
    const int bh    = blockIdx.z;
    const int m0 = mtile * 128;
    const int n0 = ntile * 256;

    const float* Ag = Qe + ((size_t)bh * Ss + m0) * EXTC;
    const float* Bg = Ke + ((size_t)bh * Ss + n0) * EXTC;

    const int kq   = tid & 7;
    const int lrow = tid >> 3;

    float acc[4][8][4];
#pragma unroll
    for (int mf = 0; mf < 4; mf++)
#pragma unroll
        for (int nf = 0; nf < 8; nf++)
#pragma unroll
            for (int j = 0; j < 4; j++) acc[mf][nf][j] = 0.f;

    float4 ra[4], rb[8];

    auto ldg = [&](int c) {
#pragma unroll
        for (int i = 0; i < 4; i++)
            ra[i] = *(const float4*)(Ag + (size_t)(lrow + i * 32) * EXTC + c * 32 + kq * 4);
#pragma unroll
        for (int i = 0; i < 8; i++)
            rb[i] = *(const float4*)(Bg + (size_t)(lrow + i * 32) * EXTC + c * 32 + kq * 4);
    };
    auto sts = [&](int buf) {
        float* ab = AsB + buf * ABUF;
#pragma unroll
        for (int i = 0; i < 4; i++)
            *(float4*)(ab + (lrow + i * 32) * ASTR + kq * 4) = ra[i];
        float* bb = BsB + buf * BBUF;
#pragma unroll
        for (int i = 0; i < 8; i++)
            *(float4*)(bb + (lrow + i * 32) * ASTR + kq * 4) = rb[i];
    };

    ldg(0);
    sts(0);
    __syncthreads();

    const int NCHUNK = EXTC / 32;   // 18
    for (int c = 0; c < NCHUNK; c++) {
        int buf = c & 1;
        if (c + 1 < NCHUNK) ldg(c + 1);

        const float* ab = AsB + buf * ABUF + (wm * 64) * ASTR;
        const float* bb = BsB + buf * BBUF + (wn * 64) * ASTR;
#pragma unroll
        for (int k8 = 0; k8 < 4; k8++) {
            int kb = k8 * 8;
            uint32_t bfr[8][2];
#pragma unroll
            for (int nf = 0; nf < 8; nf++) {
                const float* br = bb + (nf * 8 + g) * ASTR + kb;
                bfr[nf][0] = __float_as_uint(br[tig]);
                bfr[nf][1] = __float_as_uint(br[tig + 4]);
            }
#pragma unroll
            for (int mf = 0; mf < 4; mf++) {
                const float* ar = ab + (mf * 16 + g) * ASTR + kb;
                uint32_t afr[4];
                afr[0] = __float_as_uint(ar[tig]);
                afr[1] = __float_as_uint(ar[8 * ASTR + tig]);
                afr[2] = __float_as_uint(ar[tig + 4]);
                afr[3] = __float_as_uint(ar[8 * ASTR + tig + 4]);
#pragma unroll
                for (int nf = 0; nf < 8; nf++)
                    mma_tf32(acc[mf][nf], afr, bfr[nf]);
            }
        }
        if (c + 1 < NCHUNK) sts(buf ^ 1);
        __syncthreads();
    }

    // Epilogue: softmax partials (per row, per ntile, per wn-warp) + raw logits
#pragma unroll
    for (int mf = 0; mf < 4; mf++) {
        int row0 = m0 + wm * 64 + mf * 16 + g;
        float mx0 = -3.4e38f, mx1 = -3.4e38f;
#pragma unroll
        for (int nf = 0; nf < 8; nf++) {
            mx0 = fmaxf(mx0, fmaxf(acc[mf][nf][0], acc[mf][nf][1]));
            mx1 = fmaxf(mx1, fmaxf(acc[mf][nf][2], acc[mf][nf][3]));
        }
        mx0 = fmaxf(mx0, __shfl_xor_sync(0xffffffffu, mx0, 1));
        mx0 = fmaxf(mx0, __shfl_xor_sync(0xffffffffu, mx0, 2));
        mx1 = fmaxf(mx1, __shfl_xor_sync(0xffffffffu, mx1, 1));
        mx1 = fmaxf(mx1, __shfl_xor_sync(0xffffffffu, mx1, 2));

        float s0 = 0.f, s1 = 0.f;
#pragma unroll
        for (int nf = 0; nf < 8; nf++) {
            s0 += __expf(acc[mf][nf][0] - mx0) + __expf(acc[mf][nf][1] - mx0);
            s1 += __expf(acc[mf][nf][2] - mx1) + __expf(acc[mf][nf][3] - mx1);
        }
        s0 += __shfl_xor_sync(0xffffffffu, s0, 1);
        s0 += __shfl_xor_sync(0xffffffffu, s0, 2);
        s1 += __shfl_xor_sync(0xffffffffu, s1, 1);
        s1 += __shfl_xor_sync(0xffffffffu, s1, 2);

        if (tig == 0) {
            // one slot per (row, ntile, wn) -> no races, partial covers wn's 64 cols
            size_t gr0 = ((size_t)bh * Ss + row0) * NPART + ntile * 4 + wn;
            pmax[gr0] = mx0; psum[gr0] = s0;
            size_t gr1 = gr0 + 8 * NPART;       // row0 + 8
            pmax[gr1] = mx1; psum[gr1] = s1;
        }

        float* arow = attn + ((size_t)bh << 22) + (size_t)row0 * Ss
                      + n0 + wn * 64 + tig * 2;
#pragma unroll
        for (int nf = 0; nf < 8; nf++)
            *(float2*)(arow + nf * 8) = make_float2(acc[mf][nf][0], acc[mf][nf][1]);
        float* arow8 = arow + 8 * Ss;
#pragma unroll
        for (int nf = 0; nf < 8; nf++)
            *(float2*)(arow8 + nf * 8) = make_float2(acc[mf][nf][2], acc[mf][nf][3]);
    }
}

// ---------------------------------------------------------------------------
// Combine softmax partials: per row -> (max, 1/Z)
// ---------------------------------------------------------------------------
__global__ __launch_bounds__(256)
void combine_k(const float* __restrict__ pmax, const float* __restrict__ psum,
               float* __restrict__ rowm, float* __restrict__ rowz)
{
    int r = blockIdx.x * 256 + threadIdx.x;
    float m = -3.4e38f;
#pragma unroll
    for (int i = 0; i < NPART; i++) m = fmaxf(m, pmax[(size_t)r * NPART + i]);
    float z = 0.f;
#pragma unroll
    for (int i = 0; i < NPART; i++)
        z += psum[(size_t)r * NPART + i] * __expf(pmax[(size_t)r * NPART + i] - m);
    rowm[r] = m;
    rowz[r] = 1.f / z;
}

// ---------------------------------------------------------------------------
// Fused normalize + attn*V: reads raw logits, writes normalized attn back,
// computes O = attn @ V (Vt is [bh][dk][s]). BM=128, BN=64, BK=8.
// ---------------------------------------------------------------------------
__global__ __launch_bounds__(256)
void attnv_k(float* __restrict__ attn, const float* __restrict__ Vt,
             const float* __restrict__ rowm, const float* __restrict__ rowz,
             float* __restrict__ O)
{
    __shared__ float As[2][8][128];
    __shared__ float Ws[2][8][64];

    int mt = blockIdx.x, bh = blockIdx.y;
    int m0 = mt * 128;
    float* Ab = attn + ((size_t)bh << 22) + (size_t)m0 * Ss;
    const float* Wb = Vt + (size_t)bh * DKk * Ss;

    int tid = threadIdx.x;
    int tx = tid & 15, ty = tid >> 4;
    int lr = tid >> 1;
    int lc = (tid & 1) * 4;

    float rm = rowm[bh * Ss + m0 + lr];
    float rz = rowz[bh * Ss + m0 + lr];

    float acc[8][4];
#pragma unroll
    for (int i = 0; i < 8; i++)
#pragma unroll
        for (int j = 0; j < 4; j++) acc[i][j] = 0.f;

    auto ldst = [&](int buf, int kt) {
        float4 v = *(const float4*)(Ab + (size_t)lr * Ss + kt + lc);
        float4 p;
        p.x = __expf(v.x - rm) * rz;
        p.y = __expf(v.y - rm) * rz;
        p.z = __expf(v.z - rm) * rz;
        p.w = __expf(v.w - rm) * rz;
        As[buf][lc + 0][lr] = p.x;
        As[buf][lc + 1][lr] = p.y;
        As[buf][lc + 2][lr] = p.z;
        As[buf][lc + 3][lr] = p.w;
        *(float4*)(Ab + (size_t)lr * Ss + kt + lc) = p;   // writeback normalized
        if (tid < 128) {
            float4 w = *(const float4*)(Wb + (size_t)lr * Ss + kt + lc);
            Ws[buf][lc + 0][lr] = w.x;
            Ws[buf][lc + 1][lr] = w.y;
            Ws[buf][lc + 2][lr] = w.z;
            Ws[buf][lc + 3][lr] = w.w;
        }
    };

    ldst(0, 0);
    __syncthreads();

    const int nk = Ss / 8;
    for (int t = 0; t < nk; t++) {
        int buf = t & 1;
        if (t + 1 < nk) ldst(buf ^ 1, (t + 1) * 8);
#pragma unroll
        for (int kk = 0; kk < 8; kk++) {
            float a[8], b[4];
            *(float4*)&a[0] = *(const float4*)&As[buf][kk][ty * 4];
            *(float4*)&a[4] = *(const float4*)&As[buf][kk][ty * 4 + 64];
            *(float4*)&b[0] = *(const float4*)&Ws[buf][kk][tx * 4];
#pragma unroll
            for (int i = 0; i < 8; i++)
#pragma unroll
                for (int j = 0; j < 4; j++)
                    acc[i][j] = fmaf(a[i], b[j], acc[i][j]);
        }
        __syncthreads();
    }

    size_t cbase = (size_t)(bh >> 4) * ((size_t)Ss * Dd) + (size_t)(bh & 15) * 64;
#pragma unroll
    for (int gi = 0; gi < 2; gi++) {
#pragma unroll
        for (int i = 0; i < 4; i++) {
            int m = m0 + ty * 4 + gi * 64 + i;
            int n = tx * 4;
            float4 v;
            v.x = acc[gi * 4 + i][0];
            v.y = acc[gi * 4 + i][1];
            v.z = acc[gi * 4 + i][2];
            v.w = acc[gi * 4 + i][3];
            *(float4*)(O + cbase + (size_t)m * Dd + n) = v;
        }
    }
}

// ---------------------------------------------------------------------------
extern "C" void kernel_launch(void* const* d_in, const int* in_sizes, int n_in,
                              void* d_out, int out_size)
{
    const float* x  = (const float*)d_in[0];
    const float* Wq = (const float*)d_in[1];
    const float* bq = (const float*)d_in[2];
    const float* Wk = (const float*)d_in[3];
    const float* bk = (const float*)d_in[4];
    const float* Wv = (const float*)d_in[5];
    const float* bv = (const float*)d_in[6];
    const float* Wo = (const float*)d_in[7];
    const float* bo = (const float*)d_in[8];
    const float* tw = (const float*)d_in[9];
    const float* fw = (const float*)d_in[10];

    float* out  = (float*)d_out;
    float* attn = out + (size_t)Mm * Dd;

    float *qaug, *kaug, *qext, *kext, *vt, *oo, *pmax, *psum, *rowm, *rowz;
    cudaGetSymbolAddress((void**)&qaug, g_Qaug);
    cudaGetSymbolAddress((void**)&kaug, g_Kaug);
    cudaGetSymbolAddress((void**)&qext, g_Qext);
    cudaGetSymbolAddress((void**)&kext, g_Kext);
    cudaGetSymbolAddress((void**)&vt,   g_Vt);
    cudaGetSymbolAddress((void**)&oo,   g_O);
    cudaGetSymbolAddress((void**)&pmax, g_pmax);
    cudaGetSymbolAddress((void**)&psum, g_psum);
    cudaGetSymbolAddress((void**)&rowm, g_rowm);
    cudaGetSymbolAddress((void**)&rowz, g_rowz);

    static const int SCORES_SMEM = (2 * ABUF + 2 * BBUF) * 4;   // 110592
    cudaFuncSetAttribute(scores_mma_k, cudaFuncAttributeMaxDynamicSharedMemorySize,
                         SCORES_SMEM);

    dim3 blk(256);

    // projections
    sgemm_k<2, 1><<<dim3(8, 32, 1), blk>>>(x, 0, Wq, 0, bq, qaug, 0, 0, 1, Dd, Dd, Dd, 0);
    sgemm_k<2, 1><<<dim3(8, 32, 1), blk>>>(x, 0, Wk, 0, bk, kaug, 0, 0, 1, Dd, Dd, Dd, 0);
    sgemm_k<2, 2><<<dim3(8, 32, 1), blk>>>(x, 0, Wv, 0, bv, vt, 0, 0, 1, Dd, Dd, Dd, 0);

    // FFT
    twiddle_init_k<<<4, 256>>>();
    fft_k<<<dim3(BHh, 2, 32), blk>>>(qaug, kaug, tw, fw);

    // tf32 hi/lo split
    {
        int nblk = (int)(((size_t)BHh * Ss * 48) / 256);   // 12288
        convert_k<1><<<nblk, 256>>>(qaug, qext);
        convert_k<0><<<nblk, 256>>>(kaug, kext);
    }

    // scores (tensor cores) + softmax partials; raw logits into attn region
    scores_mma_k<<<dim3(8, 16, BHh), blk, SCORES_SMEM>>>(qext, kext, attn, pmax, psum);

    // combine partials -> per-row (max, 1/Z)
    combine_k<<<(BHh * Ss) / 256, 256>>>(pmax, psum, rowm, rowz);

    // fused normalize + attn*V
    attnv_k<<<dim3(16, BHh), blk>>>(attn, vt, rowm, rowz, oo);

    // out projection
    sgemm_k<2, 0><<<dim3(8, 32, 1), blk>>>(oo, 0, Wo, 0, bo, out, 0, 0, 1, Dd, Dd, Dd, Dd);
}

// round 5
// speedup vs baseline: 1.1335x; 1.0656x over previous
#include <cuda_runtime.h>
#include <cuda_bf16.h>
#include <math.h>
#include <stdint.h>

// Problem constants
#define Bb   2
#define Ss   2048
#define Dd   1024
#define Hh   16
#define DKk  64
#define AUGC 192              // [time | Re | Im]
#define F32C 192              // tf32 hi lanes
#define B16C 384              // bf16 lanes: Q=[ql|qh], K=[kh|kl]
#define BHh  (Bb * Hh)        // 32
#define Mm   (Bb * Ss)        // 4096
#define NPART 32              // softmax partials per row: 8 ntiles x 4 wn-warps

// Scratch
__device__ float          g_Qaug[(size_t)BHh * Ss * AUGC];
__device__ float          g_Kaug[(size_t)BHh * Ss * AUGC];
__device__ float          g_Qf32[(size_t)BHh * Ss * F32C];
__device__ float          g_Kf32[(size_t)BHh * Ss * F32C];
__device__ __nv_bfloat16  g_Qb16[(size_t)BHh * Ss * B16C];
__device__ __nv_bfloat16  g_Kb16[(size_t)BHh * Ss * B16C];
__device__ float          g_Vt  [(size_t)BHh * DKk * Ss];
__device__ float          g_O   [(size_t)Mm * Dd];
__device__ float          g_pmax[(size_t)BHh * Ss * NPART];
__device__ float          g_psum[(size_t)BHh * Ss * NPART];
__device__ float          g_rowm[(size_t)BHh * Ss];
__device__ float          g_rowz[(size_t)BHh * Ss];
__device__ float2         g_twid[1024];

// ---------------------------------------------------------------------------
// Twiddle init (fp64-accurate)
// ---------------------------------------------------------------------------
__global__ void twiddle_init_k() {
    int t = blockIdx.x * blockDim.x + threadIdx.x;
    if (t < 1024) {
        double ang = -2.0 * 3.14159265358979323846 * (double)t / 2048.0;
        double s, c;
        sincos(ang, &s, &c);
        g_twid[t] = make_float2((float)c, (float)s);
    }
}

// ---------------------------------------------------------------------------
// Generic fp32 SGEMM (known-good): C = A * W^T (+bias)
// ---------------------------------------------------------------------------
template<int NG, int MODE>
__global__ __launch_bounds__(256)
void sgemm_k(const float* __restrict__ A, size_t saZ,
             const float* __restrict__ W, size_t swZ,
             const float* __restrict__ bias,
             float* __restrict__ C, size_t scB1, size_t scB2, int Hdiv,
             int K, int lda, int ldw, int ldc)
{
    const int BM = 128, BK = 8;
    const int BN = 64 * NG;
    __shared__ float As[2][BK][BM];
    __shared__ float Ws[2][BK][BN];

    int z = blockIdx.z;
    const float* Ab = A + (size_t)z * saZ;
    const float* Wb = W + (size_t)z * swZ;
    size_t cbase = (size_t)(z / Hdiv) * scB1 + (size_t)(z % Hdiv) * scB2;

    int m0 = blockIdx.y * BM;
    int n0 = blockIdx.x * BN;
    int tid = threadIdx.x;
    int tx = tid & 15, ty = tid >> 4;
    int lr = tid >> 1;
    int lc = (tid & 1) * 4;

    float acc[8][4 * NG];
#pragma unroll
    for (int i = 0; i < 8; i++)
#pragma unroll
        for (int j = 0; j < 4 * NG; j++) acc[i][j] = 0.f;

    auto ldst = [&](int buf, int kt) {
        float4 av = *(const float4*)(Ab + (size_t)(m0 + lr) * lda + kt + lc);
        As[buf][lc + 0][lr] = av.x;
        As[buf][lc + 1][lr] = av.y;
        As[buf][lc + 2][lr] = av.z;
        As[buf][lc + 3][lr] = av.w;
        if (NG == 2 || tid < 128) {
            float4 wv = *(const float4*)(Wb + (size_t)(n0 + lr) * ldw + kt + lc);
            Ws[buf][lc + 0][lr] = wv.x;
            Ws[buf][lc + 1][lr] = wv.y;
            Ws[buf][lc + 2][lr] = wv.z;
            Ws[buf][lc + 3][lr] = wv.w;
        }
    };

    ldst(0, 0);
    __syncthreads();

    int nk = K / BK;
    for (int t = 0; t < nk; t++) {
        int buf = t & 1;
        if (t + 1 < nk) ldst(buf ^ 1, (t + 1) * BK);
#pragma unroll
        for (int kk = 0; kk < BK; kk++) {
            float a[8], b[4 * NG];
            *(float4*)&a[0] = *(const float4*)&As[buf][kk][ty * 4];
            *(float4*)&a[4] = *(const float4*)&As[buf][kk][ty * 4 + 64];
            *(float4*)&b[0] = *(const float4*)&Ws[buf][kk][tx * 4];
            if (NG == 2)
                *(float4*)&b[4] = *(const float4*)&Ws[buf][kk][tx * 4 + 64];
#pragma unroll
            for (int i = 0; i < 8; i++)
#pragma unroll
                for (int j = 0; j < 4 * NG; j++)
                    acc[i][j] = fmaf(a[i], b[j], acc[i][j]);
        }
        __syncthreads();
    }

#pragma unroll
    for (int gi = 0; gi < 2; gi++) {
#pragma unroll
        for (int i = 0; i < 4; i++) {
            int m = m0 + ty * 4 + gi * 64 + i;
#pragma unroll
            for (int gj = 0; gj < NG; gj++) {
                int n = n0 + tx * 4 + gj * 64;
                float4 v;
                v.x = acc[gi * 4 + i][gj * 4 + 0];
                v.y = acc[gi * 4 + i][gj * 4 + 1];
                v.z = acc[gi * 4 + i][gj * 4 + 2];
                v.w = acc[gi * 4 + i][gj * 4 + 3];
                if (bias) {
                    v.x += bias[n + 0]; v.y += bias[n + 1];
                    v.z += bias[n + 2]; v.w += bias[n + 3];
                }
                if (MODE == 0) {
                    *(float4*)(C + cbase + (size_t)m * ldc + n) = v;
                } else if (MODE == 1) {
                    int bb = m >> 11, s = m & 2047;
                    int hh = n >> 6,  d = n & 63;
                    *(float4*)(C + ((size_t)((bb * 16 + hh) * 2048 + s)) * AUGC + d) = v;
                } else {
                    int bb = m >> 11, s = m & 2047;
                    int hh = n >> 6,  d = n & 63;
                    float* cp = C + ((size_t)(bb * 16 + hh) * 64 + d) * 2048 + s;
                    cp[0 * 2048] = v.x; cp[1 * 2048] = v.y;
                    cp[2 * 2048] = v.z; cp[3 * 2048] = v.w;
                }
            }
        }
    }
}

// ---------------------------------------------------------------------------
// FFT (known-good)
// ---------------------------------------------------------------------------
__global__ __launch_bounds__(256)
void fft_k(float* qaug, float* kaug, const float* twp, const float* fwp)
{
    __shared__ float  sr[2][2048];
    __shared__ float  si[2][2048];
    __shared__ float2 tw[1024];

    int bh     = blockIdx.x;
    int tensor = blockIdx.y;
    int dk0    = blockIdx.z * 2;
    float* base = (tensor == 0 ? qaug : kaug) + (size_t)bh * Ss * AUGC;
    int tid = threadIdx.x;

    for (int t = tid; t < 1024; t += 256) tw[t] = g_twid[t];

    for (int idx = tid; idx < 2 * Ss; idx += 256) {
        int l = idx & 1;
        int s = idx >> 1;
        float v = base[(size_t)s * AUGC + dk0 + l];
        int rs = __brev((unsigned)s) >> 21;
        sr[l][rs] = v;
        si[l][rs] = 0.f;
    }
    __syncthreads();

    for (int len = 2; len <= 2048; len <<= 1) {
        int half = len >> 1;
        int step = 2048 / len;
        for (int idx = tid; idx < 2048; idx += 256) {
            int l   = idx >> 10;
            int bix = idx & 1023;
            int grp = bix / half;
            int pos = bix - grp * half;
            int i0 = grp * len + pos;
            int i1 = i0 + half;
            float2 w = tw[pos * step];
            float xr = sr[l][i1], xi = si[l][i1];
            float tr = xr * w.x - xi * w.y;
            float ti = xr * w.y + xi * w.x;
            float ur = sr[l][i0], ui = si[l][i0];
            sr[l][i0] = ur + tr;  si[l][i0] = ui + ti;
            sr[l][i1] = ur - tr;  si[l][i1] = ui - ti;
        }
        __syncthreads();
    }

    float ft, ff;
    if (tensor == 0) { ft = twp[0] * 0.125f; ff = fwp[0] * 0.125f; }
    else             { ft = 1.f;             ff = 1.f; }

    for (int idx = tid; idx < 2 * Ss; idx += 256) {
        int l = idx & 1;
        int s = idx >> 1;
        size_t o = (size_t)s * AUGC + dk0 + l;
        if (tensor == 0) base[o] *= ft;
        base[o + 64]  = sr[l][s] * ff;
        base[o + 128] = si[l][s] * ff;
    }
}

// ---------------------------------------------------------------------------
// Convert aug (192 f32) -> tf32 hi (192 f32) + bf16 lanes (384 bf16)
// Q (QMODE=1): bf16 = [bf16(x-hi) | bf16(x)]
// K (QMODE=0): bf16 = [bf16(x)    | bf16(x-hi)]
// ---------------------------------------------------------------------------
__device__ __forceinline__ float tf32r(float x) {
    uint32_t u;
    asm("cvt.rna.tf32.f32 %0, %1;" : "=r"(u) : "f"(x));
    return __uint_as_float(u);
}
__device__ __forceinline__ uint32_t packbf(float a, float b) {
    __nv_bfloat162 p = __float22bfloat162_rn(make_float2(a, b));
    return *reinterpret_cast<uint32_t*>(&p);
}
template<int QMODE>
__global__ __launch_bounds__(256)
void convert_k(const float* __restrict__ src, float* __restrict__ dsth,
               __nv_bfloat16* __restrict__ dstb)
{
    size_t i4 = (size_t)blockIdx.x * 256 + threadIdx.x;   // 48 float4 per row
    size_t row = i4 / 48;
    int c4 = (int)(i4 % 48);
    float4 x = ((const float4*)src)[i4];
    float4 h, l;
    h.x = tf32r(x.x); l.x = x.x - h.x;
    h.y = tf32r(x.y); l.y = x.y - h.y;
    h.z = tf32r(x.z); l.z = x.z - h.z;
    h.w = tf32r(x.w); l.w = x.w - h.w;
    *(float4*)(dsth + row * F32C + c4 * 4) = h;

    uint2 lo, hi;
    lo.x = packbf(l.x, l.y); lo.y = packbf(l.z, l.w);
    hi.x = packbf(x.x, x.y); hi.y = packbf(x.z, x.w);
    __nv_bfloat16* brow = dstb + row * B16C;
    if (QMODE) {   // Q: [ql | qh]
        *(uint2*)(brow + c4 * 4)       = lo;
        *(uint2*)(brow + 192 + c4 * 4) = hi;
    } else {       // K: [kh | kl]
        *(uint2*)(brow + c4 * 4)       = hi;
        *(uint2*)(brow + 192 + c4 * 4) = lo;
    }
}

// ---------------------------------------------------------------------------
// Scores: tf32 hi*hi (K=192) + bf16 corrections (K=384), CTA tile 128x256,
// 8 warps @64x64. Epilogue: raw logits + per-(row,ntile,wn) softmax partials.
// grid = (8 ntiles, 16 mtiles, 32 bh), 256 threads, dyn smem 110592B
// ---------------------------------------------------------------------------
#define ASTR 36
#define ABUF (128 * ASTR)
#define BBUF (256 * ASTR)
// bf16 stage (aliased onto same smem): row stride 40 bf16 = 80B
#define A16BYTES (128 * 80)    // 10240
#define B16BYTES (256 * 80)    // 20480

__device__ __forceinline__ void mma_tf32(float c[4], const uint32_t a[4],
                                         const uint32_t b[2]) {
    asm volatile(
        "mma.sync.aligned.m16n8k8.row.col.f32.tf32.tf32.f32 "
        "{%0,%1,%2,%3}, {%4,%5,%6,%7}, {%8,%9}, {%0,%1,%2,%3};"
        : "+f"(c[0]), "+f"(c[1]), "+f"(c[2]), "+f"(c[3])
        : "r"(a[0]), "r"(a[1]), "r"(a[2]), "r"(a[3]), "r"(b[0]), "r"(b[1]));
}
__device__ __forceinline__ void mma_bf16(float c[4], const uint32_t a[4],
                                         const uint32_t b[2]) {
    asm volatile(
        "mma.sync.aligned.m16n8k16.row.col.f32.bf16.bf16.f32 "
        "{%0,%1,%2,%3}, {%4,%5,%6,%7}, {%8,%9}, {%0,%1,%2,%3};"
        : "+f"(c[0]), "+f"(c[1]), "+f"(c[2]), "+f"(c[3])
        : "r"(a[0]), "r"(a[1]), "r"(a[2]), "r"(a[3]), "r"(b[0]), "r"(b[1]));
}

__global__ __launch_bounds__(256, 1)
void scores_mma_k(const float* __restrict__ Qh, const float* __restrict__ Kh,
                  const __nv_bfloat16* __restrict__ Qb,
                  const __nv_bfloat16* __restrict__ Kb,
                  float* __restrict__ attn,
                  float* __restrict__ pmax, float* __restrict__ psum)
{
    extern __shared__ char smc[];
    float* AsB = (float*)smc;               // f32 stage: [2][128][36]
    float* BsB = (float*)smc + 2 * ABUF;    //            [2][256][36]

    const int tid  = threadIdx.x;
    const int wid  = tid >> 5;
    const int lane = tid & 31;
    const int g    = lane >> 2;
    const int tig  = lane & 3;
    const int wm   = wid >> 2;
    const int wn   = wid & 3;

    const int ntile = blockIdx.x;
    const int mtile = blockIdx.y;
    const int bh    = blockIdx.z;
    const int m0 = mtile * 128;
    const int n0 = ntile * 256;

    const float* Ag = Qh + ((size_t)bh * Ss + m0) * F32C;
    const float* Bg = Kh + ((size_t)bh * Ss + n0) * F32C;
    const __nv_bfloat16* Agb = Qb + ((size_t)bh * Ss + m0) * B16C;
    const __nv_bfloat16* Bgb = Kb + ((size_t)bh * Ss + n0) * B16C;

    const int kq   = tid & 7;
    const int lrow = tid >> 3;

    float acc[4][8][4];
#pragma unroll
    for (int mf = 0; mf < 4; mf++)
#pragma unroll
        for (int nf = 0; nf < 8; nf++)
#pragma unroll
            for (int j = 0; j < 4; j++) acc[mf][nf][j] = 0.f;

    // ================= Phase 1: tf32 hi*hi, K=192, 6 chunks of 32 ==========
    {
        float4 ra[4], rb[8];
        auto ldg = [&](int c) {
#pragma unroll
            for (int i = 0; i < 4; i++)
                ra[i] = *(const float4*)(Ag + (size_t)(lrow + i * 32) * F32C + c * 32 + kq * 4);
#pragma unroll
            for (int i = 0; i < 8; i++)
                rb[i] = *(const float4*)(Bg + (size_t)(lrow + i * 32) * F32C + c * 32 + kq * 4);
        };
        auto sts = [&](int buf) {
            float* ab = AsB + buf * ABUF;
#pragma unroll
            for (int i = 0; i < 4; i++)
                *(float4*)(ab + (lrow + i * 32) * ASTR + kq * 4) = ra[i];
            float* bb = BsB + buf * BBUF;
#pragma unroll
            for (int i = 0; i < 8; i++)
                *(float4*)(bb + (lrow + i * 32) * ASTR + kq * 4) = rb[i];
        };

        ldg(0);
        sts(0);
        __syncthreads();

        const int NCH = F32C / 32;   // 6
        for (int c = 0; c < NCH; c++) {
            int buf = c & 1;
            if (c + 1 < NCH) ldg(c + 1);

            const float* ab = AsB + buf * ABUF + (wm * 64) * ASTR;
            const float* bb = BsB + buf * BBUF + (wn * 64) * ASTR;
#pragma unroll
            for (int k8 = 0; k8 < 4; k8++) {
                int kb = k8 * 8;
                uint32_t bfr[8][2];
#pragma unroll
                for (int nf = 0; nf < 8; nf++) {
                    const float* br = bb + (nf * 8 + g) * ASTR + kb;
                    bfr[nf][0] = __float_as_uint(br[tig]);
                    bfr[nf][1] = __float_as_uint(br[tig + 4]);
                }
#pragma unroll
                for (int mf = 0; mf < 4; mf++) {
                    const float* ar = ab + (mf * 16 + g) * ASTR + kb;
                    uint32_t afr[4];
                    afr[0] = __float_as_uint(ar[tig]);
                    afr[1] = __float_as_uint(ar[8 * ASTR + tig]);
                    afr[2] = __float_as_uint(ar[tig + 4]);
                    afr[3] = __float_as_uint(ar[8 * ASTR + tig + 4]);
#pragma unroll
                    for (int nf = 0; nf < 8; nf++)
                        mma_tf32(acc[mf][nf], afr, bfr[nf]);
                }
            }
            if (c + 1 < NCH) sts(buf ^ 1);
            __syncthreads();
        }
    }

    // ================= Phase 2: bf16 corrections, K=384, 12 chunks of 32 ====
    {
        const int r16 = tid >> 3, t8 = tid & 7;   // 8B per thread, 32 bf16/row-chunk
        uint2 ra16[4], rb16[8];
        auto ldg16 = [&](int c) {
#pragma unroll
            for (int i = 0; i < 4; i++)
                ra16[i] = *(const uint2*)(Agb + (size_t)(r16 + i * 32) * B16C + c * 32 + t8 * 4);
#pragma unroll
            for (int i = 0; i < 8; i++)
                rb16[i] = *(const uint2*)(Bgb + (size_t)(r16 + i * 32) * B16C + c * 32 + t8 * 4);
        };
        auto sts16 = [&](int b) {
            char* a16 = smc + b * A16BYTES;
#pragma unroll
            for (int i = 0; i < 4; i++)
                *(uint2*)(a16 + (r16 + i * 32) * 80 + t8 * 8) = ra16[i];
            char* b16 = smc + 2 * A16BYTES + b * B16BYTES;
#pragma unroll
            for (int i = 0; i < 8; i++)
                *(uint2*)(b16 + (r16 + i * 32) * 80 + t8 * 8) = rb16[i];
        };

        ldg16(0);
        sts16(0);
        __syncthreads();

        const int NCH = B16C / 32;   // 12
        for (int c = 0; c < NCH; c++) {
            int buf = c & 1;
            if (c + 1 < NCH) ldg16(c + 1);

            const char* a16 = smc + buf * A16BYTES + (wm * 64) * 80;
            const char* b16 = smc + 2 * A16BYTES + buf * B16BYTES + (wn * 64) * 80;
#pragma unroll
            for (int st = 0; st < 2; st++) {      // 2 x k16 per 32-col chunk
                int kb = st * 32;                 // bytes
                uint32_t bfr[8][2];
#pragma unroll
                for (int nf = 0; nf < 8; nf++) {
                    const char* br = b16 + (nf * 8 + g) * 80 + kb + tig * 4;
                    bfr[nf][0] = *(const uint32_t*)br;
                    bfr[nf][1] = *(const uint32_t*)(br + 16);
                }
#pragma unroll
                for (int mf = 0; mf < 4; mf++) {
                    const char* ar = a16 + (mf * 16 + g) * 80 + kb + tig * 4;
                    uint32_t afr[4];
                    afr[0] = *(const uint32_t*)ar;
                    afr[1] = *(const uint32_t*)(ar + 8 * 80);
                    afr[2] = *(const uint32_t*)(ar + 16);
                    afr[3] = *(const uint32_t*)(ar + 8 * 80 + 16);
#pragma unroll
                    for (int nf = 0; nf < 8; nf++)
                        mma_bf16(acc[mf][nf], afr, bfr[nf]);
                }
            }
            if (c + 1 < NCH) sts16(buf ^ 1);
            __syncthreads();
        }
    }

    // ============ Epilogue: softmax partials + raw logit stores =============
#pragma unroll
    for (int mf = 0; mf < 4; mf++) {
        int row0 = m0 + wm * 64 + mf * 16 + g;
        float mx0 = -3.4e38f, mx1 = -3.4e38f;
#pragma unroll
        for (int nf = 0; nf < 8; nf++) {
            mx0 = fmaxf(mx0, fmaxf(acc[mf][nf][0], acc[mf][nf][1]));
            mx1 = fmaxf(mx1, fmaxf(acc[mf][nf][2], acc[mf][nf][3]));
        }
        mx0 = fmaxf(mx0, __shfl_xor_sync(0xffffffffu, mx0, 1));
        mx0 = fmaxf(mx0, __shfl_xor_sync(0xffffffffu, mx0, 2));
        mx1 = fmaxf(mx1, __shfl_xor_sync(0xffffffffu, mx1, 1));
        mx1 = fmaxf(mx1, __shfl_xor_sync(0xffffffffu, mx1, 2));

        float s0 = 0.f, s1 = 0.f;
#pragma unroll
        for (int nf = 0; nf < 8; nf++) {
            s0 += __expf(acc[mf][nf][0] - mx0) + __expf(acc[mf][nf][1] - mx0);
            s1 += __expf(acc[mf][nf][2] - mx1) + __expf(acc[mf][nf][3] - mx1);
        }
        s0 += __shfl_xor_sync(0xffffffffu, s0, 1);
        s0 += __shfl_xor_sync(0xffffffffu, s0, 2);
        s1 += __shfl_xor_sync(0xffffffffu, s1, 1);
        s1 += __shfl_xor_sync(0xffffffffu, s1, 2);

        if (tig == 0) {
            size_t gr0 = ((size_t)bh * Ss + row0) * NPART + ntile * 4 + wn;
            pmax[gr0] = mx0; psum[gr0] = s0;
            size_t gr1 = gr0 + 8 * NPART;       // row0 + 8
            pmax[gr1] = mx1; psum[gr1] = s1;
        }

        float* arow = attn + ((size_t)bh << 22) + (size_t)row0 * Ss
                      + n0 + wn * 64 + tig * 2;
#pragma unroll
        for (int nf = 0; nf < 8; nf++)
            *(float2*)(arow + nf * 8) = make_float2(acc[mf][nf][0], acc[mf][nf][1]);
        float* arow8 = arow + 8 * Ss;
#pragma unroll
        for (int nf = 0; nf < 8; nf++)
            *(float2*)(arow8 + nf * 8) = make_float2(acc[mf][nf][2], acc[mf][nf][3]);
    }
}

// ---------------------------------------------------------------------------
// Combine softmax partials: per row -> (max, 1/Z)
// ---------------------------------------------------------------------------
__global__ __launch_bounds__(256)
void combine_k(const float* __restrict__ pmax, const float* __restrict__ psum,
               float* __restrict__ rowm, float* __restrict__ rowz)
{
    int r = blockIdx.x * 256 + threadIdx.x;
    float m = -3.4e38f;
#pragma unroll
    for (int i = 0; i < NPART; i++) m = fmaxf(m, pmax[(size_t)r * NPART + i]);
    float z = 0.f;
#pragma unroll
    for (int i = 0; i < NPART; i++)
        z += psum[(size_t)r * NPART + i] * __expf(pmax[(size_t)r * NPART + i] - m);
    rowm[r] = m;
    rowz[r] = 1.f / z;
}

// ---------------------------------------------------------------------------
// Fused normalize + attn*V (known-good)
// ---------------------------------------------------------------------------
__global__ __launch_bounds__(256)
void attnv_k(float* __restrict__ attn, const float* __restrict__ Vt,
             const float* __restrict__ rowm, const float* __restrict__ rowz,
             float* __restrict__ O)
{
    __shared__ float As[2][8][128];
    __shared__ float Ws[2][8][64];

    int mt = blockIdx.x, bh = blockIdx.y;
    int m0 = mt * 128;
    float* Ab = attn + ((size_t)bh << 22) + (size_t)m0 * Ss;
    const float* Wb = Vt + (size_t)bh * DKk * Ss;

    int tid = threadIdx.x;
    int tx = tid & 15, ty = tid >> 4;
    int lr = tid >> 1;
    int lc = (tid & 1) * 4;

    float rm = rowm[bh * Ss + m0 + lr];
    float rz = rowz[bh * Ss + m0 + lr];

    float acc[8][4];
#pragma unroll
    for (int i = 0; i < 8; i++)
#pragma unroll
        for (int j = 0; j < 4; j++) acc[i][j] = 0.f;

    auto ldst = [&](int buf, int kt) {
        float4 v = *(const float4*)(Ab + (size_t)lr * Ss + kt + lc);
        float4 p;
        p.x = __expf(v.x - rm) * rz;
        p.y = __expf(v.y - rm) * rz;
        p.z = __expf(v.z - rm) * rz;
        p.w = __expf(v.w - rm) * rz;
        As[buf][lc + 0][lr] = p.x;
        As[buf][lc + 1][lr] = p.y;
        As[buf][lc + 2][lr] = p.z;
        As[buf][lc + 3][lr] = p.w;
        *(float4*)(Ab + (size_t)lr * Ss + kt + lc) = p;   // writeback normalized
        if (tid < 128) {
            float4 w = *(const float4*)(Wb + (size_t)lr * Ss + kt + lc);
            Ws[buf][lc + 0][lr] = w.x;
            Ws[buf][lc + 1][lr] = w.y;
            Ws[buf][lc + 2][lr] = w.z;
            Ws[buf][lc + 3][lr] = w.w;
        }
    };

    ldst(0, 0);
    __syncthreads();

    const int nk = Ss / 8;
    for (int t = 0; t < nk; t++) {
        int buf = t & 1;
        if (t + 1 < nk) ldst(buf ^ 1, (t + 1) * 8);
#pragma unroll
        for (int kk = 0; kk < 8; kk++) {
            float a[8], b[4];
            *(float4*)&a[0] = *(const float4*)&As[buf][kk][ty * 4];
            *(float4*)&a[4] = *(const float4*)&As[buf][kk][ty * 4 + 64];
            *(float4*)&b[0] = *(const float4*)&Ws[buf][kk][tx * 4];
#pragma unroll
            for (int i = 0; i < 8; i++)
#pragma unroll
                for (int j = 0; j < 4; j++)
                    acc[i][j] = fmaf(a[i], b[j], acc[i][j]);
        }
        __syncthreads();
    }

    size_t cbase = (size_t)(bh >> 4) * ((size_t)Ss * Dd) + (size_t)(bh & 15) * 64;
#pragma unroll
    for (int gi = 0; gi < 2; gi++) {
#pragma unroll
        for (int i = 0; i < 4; i++) {
            int m = m0 + ty * 4 + gi * 64 + i;
            int n = tx * 4;
            float4 v;
            v.x = acc[gi * 4 + i][0];
            v.y = acc[gi * 4 + i][1];
            v.z = acc[gi * 4 + i][2];
            v.w = acc[gi * 4 + i][3];
            *(float4*)(O + cbase + (size_t)m * Dd + n) = v;
        }
    }
}

// ---------------------------------------------------------------------------
extern "C" void kernel_launch(void* const* d_in, const int* in_sizes, int n_in,
                              void* d_out, int out_size)
{
    const float* x  = (const float*)d_in[0];
    const float* Wq = (const float*)d_in[1];
    const float* bq = (const float*)d_in[2];
    const float* Wk = (const float*)d_in[3];
    const float* bk = (const float*)d_in[4];
    const float* Wv = (const float*)d_in[5];
    const float* bv = (const float*)d_in[6];
    const float* Wo = (const float*)d_in[7];
    const float* bo = (const float*)d_in[8];
    const float* tw = (const float*)d_in[9];
    const float* fw = (const float*)d_in[10];

    float* out  = (float*)d_out;
    float* attn = out + (size_t)Mm * Dd;

    float *qaug, *kaug, *qf, *kf, *vt, *oo, *pmax, *psum, *rowm, *rowz;
    __nv_bfloat16 *qb, *kb;
    cudaGetSymbolAddress((void**)&qaug, g_Qaug);
    cudaGetSymbolAddress((void**)&kaug, g_Kaug);
    cudaGetSymbolAddress((void**)&qf,   g_Qf32);
    cudaGetSymbolAddress((void**)&kf,   g_Kf32);
    cudaGetSymbolAddress((void**)&qb,   g_Qb16);
    cudaGetSymbolAddress((void**)&kb,   g_Kb16);
    cudaGetSymbolAddress((void**)&vt,   g_Vt);
    cudaGetSymbolAddress((void**)&oo,   g_O);
    cudaGetSymbolAddress((void**)&pmax, g_pmax);
    cudaGetSymbolAddress((void**)&psum, g_psum);
    cudaGetSymbolAddress((void**)&rowm, g_rowm);
    cudaGetSymbolAddress((void**)&rowz, g_rowz);

    static const int SCORES_SMEM = (2 * ABUF + 2 * BBUF) * 4;   // 110592
    cudaFuncSetAttribute(scores_mma_k, cudaFuncAttributeMaxDynamicSharedMemorySize,
                         SCORES_SMEM);

    dim3 blk(256);

    // projections
    sgemm_k<2, 1><<<dim3(8, 32, 1), blk>>>(x, 0, Wq, 0, bq, qaug, 0, 0, 1, Dd, Dd, Dd, 0);
    sgemm_k<2, 1><<<dim3(8, 32, 1), blk>>>(x, 0, Wk, 0, bk, kaug, 0, 0, 1, Dd, Dd, Dd, 0);
    sgemm_k<2, 2><<<dim3(8, 32, 1), blk>>>(x, 0, Wv, 0, bv, vt, 0, 0, 1, Dd, Dd, Dd, 0);

    // FFT
    twiddle_init_k<<<4, 256>>>();
    fft_k<<<dim3(BHh, 2, 32), blk>>>(qaug, kaug, tw, fw);

    // mixed-precision split
    {
        int nblk = (int)(((size_t)BHh * Ss * 48) / 256);   // 12288
        convert_k<1><<<nblk, 256>>>(qaug, qf, qb);
        convert_k<0><<<nblk, 256>>>(kaug, kf, kb);
    }

    // scores (tf32 + bf16 corrections) + softmax partials
    scores_mma_k<<<dim3(8, 16, BHh), blk, SCORES_SMEM>>>(qf, kf, qb, kb,
                                                         attn, pmax, psum);

    // combine partials -> per-row (max, 1/Z)
    combine_k<<<(BHh * Ss) / 256, 256>>>(pmax, psum, rowm, rowz);

    // fused normalize + attn*V
    attnv_k<<<dim3(16, BHh), blk>>>(attn, vt, rowm, rowz, oo);

    // out projection
    sgemm_k<2, 0><<<dim3(8, 32, 1), blk>>>(oo, 0, Wo, 0, bo, out, 0, 0, 1, Dd, Dd, Dd, Dd);
}